// round 3
// baseline (speedup 1.0000x reference)
#include <cuda_runtime.h>
#include <math.h>

// ---------------- problem constants ----------------
static constexpr int Bn = 32, Cn = 32, Sn = 16, En = 1280, Rn = 256;
static constexpr int Hn = 4, HDn = 64, FFn = 512;
static constexpr int BC = Bn * Cn;               // 1024 tokens
static constexpr int HEAD_IN = Cn * Rn + 64 + 32 + 3;  // 8291
static constexpr int QKVn = 3 * Rn;              // 768

// ---------------- scratch (device globals; no allocation allowed) ----------------
__device__ __align__(16) float g_agg[BC * En];
__device__ __align__(16) float g_x0[BC * Rn];
__device__ __align__(16) float g_qkv[BC * QKVn];
__device__ __align__(16) float g_att[BC * Rn];
__device__ __align__(16) float g_oproj[BC * Rn];
__device__ __align__(16) float g_x1[BC * Rn];
__device__ __align__(16) float g_ff1[BC * FFn];
__device__ __align__(16) float g_ff2[BC * Rn];
__device__ __align__(16) float g_x2[BC * Rn];
__device__ __align__(16) float g_h[Bn * 128];

// ---------------- 1) ragged softmax aggregation -> agg[BC, E] ----------------
// one block per (b,c); 320 threads, each owns one float4 column chunk (1280/4=320)
__global__ void agg_kernel(const float* __restrict__ embs,
                           const int* __restrict__ idx,
                           const int* __restrict__ mask,   // bool -> int32 in harness
                           const float* __restrict__ fw) {
    int bc = blockIdx.x;
    __shared__ float attn[Sn];
    int t = threadIdx.x;
    if (t == 0) {
        float w[Sn];
        int any = 0;
        #pragma unroll
        for (int s = 0; s < Sn; s++) {
            int m = mask[bc * Sn + s];
            any |= m;
            w[s] = m ? fw[idx[bc * Sn + s]] : -1e30f;
        }
        float mx = -1e30f;
        #pragma unroll
        for (int s = 0; s < Sn; s++) mx = fmaxf(mx, w[s]);
        float e[Sn], sum = 0.f;
        #pragma unroll
        for (int s = 0; s < Sn; s++) { e[s] = expf(w[s] - mx); sum += e[s]; }
        float inv = any ? (1.f / sum) : 0.f;   // empty segment -> zeros (matches reference)
        #pragma unroll
        for (int s = 0; s < Sn; s++) attn[s] = e[s] * inv;
    }
    __syncthreads();
    const float4* ebase = (const float4*)(embs + (size_t)bc * Sn * En);
    float4 acc = make_float4(0.f, 0.f, 0.f, 0.f);
    #pragma unroll
    for (int s = 0; s < Sn; s++) {
        float a = attn[s];
        float4 v = ebase[s * (En / 4) + t];
        acc.x = fmaf(a, v.x, acc.x);
        acc.y = fmaf(a, v.y, acc.y);
        acc.z = fmaf(a, v.z, acc.z);
        acc.w = fmaf(a, v.w, acc.w);
    }
    ((float4*)(g_agg + (size_t)bc * En))[t] = acc;
}

// ---------------- generic tiled fp32 GEMM: C[M,N] = A[M,K] @ B[N,K]^T + bias ----------------
// requires M%BM==0, N%BN==0, K%16==0, threads = (BM/TM)*(BN/TN) == 256
template <int BM, int BN, int TM, int TN, bool RELU>
__global__ void gemm_kernel(const float* __restrict__ A,
                            const float* __restrict__ B,
                            const float* __restrict__ bias,
                            float* __restrict__ C,
                            int M, int N, int K) {
    constexpr int BK = 16;
    constexpr int THREADS = (BM / TM) * (BN / TN);
    __shared__ float As[BM][BK + 1];
    __shared__ float Bs[BN][BK + 1];
    const int tid = threadIdx.x;
    const int bn0 = blockIdx.x * BN;
    const int bm0 = blockIdx.y * BM;
    const int tx = tid % (BN / TN);
    const int ty = tid / (BN / TN);

    float acc[TM][TN];
    #pragma unroll
    for (int i = 0; i < TM; i++)
        #pragma unroll
        for (int j = 0; j < TN; j++) acc[i][j] = 0.f;

    for (int k0 = 0; k0 < K; k0 += BK) {
        for (int i = tid * 4; i < BM * BK; i += THREADS * 4) {
            int r = i / BK, c = i % BK;
            float4 v = *(const float4*)&A[(size_t)(bm0 + r) * K + k0 + c];
            As[r][c] = v.x; As[r][c + 1] = v.y; As[r][c + 2] = v.z; As[r][c + 3] = v.w;
        }
        for (int i = tid * 4; i < BN * BK; i += THREADS * 4) {
            int r = i / BK, c = i % BK;
            float4 v = *(const float4*)&B[(size_t)(bn0 + r) * K + k0 + c];
            Bs[r][c] = v.x; Bs[r][c + 1] = v.y; Bs[r][c + 2] = v.z; Bs[r][c + 3] = v.w;
        }
        __syncthreads();
        #pragma unroll
        for (int kk = 0; kk < BK; kk++) {
            float a[TM], b[TN];
            #pragma unroll
            for (int i = 0; i < TM; i++) a[i] = As[ty * TM + i][kk];
            #pragma unroll
            for (int j = 0; j < TN; j++) b[j] = Bs[tx * TN + j][kk];
            #pragma unroll
            for (int i = 0; i < TM; i++)
                #pragma unroll
                for (int j = 0; j < TN; j++) acc[i][j] = fmaf(a[i], b[j], acc[i][j]);
        }
        __syncthreads();
    }
    #pragma unroll
    for (int i = 0; i < TM; i++) {
        int m = bm0 + ty * TM + i;
        #pragma unroll
        for (int j = 0; j < TN; j++) {
            int n = bn0 + tx * TN + j;
            float v = acc[i][j] + bias[n];
            if (RELU) v = fmaxf(v, 0.f);
            C[(size_t)m * N + n] = v;
        }
    }
}

// ---------------- 3) attention: one block per (b, h) ----------------
__global__ void attn_kernel(const float* __restrict__ qkv, float* __restrict__ o) {
    int b = blockIdx.x / Hn;
    int h = blockIdx.x % Hn;
    __shared__ float qs[Cn][HDn], ks[Cn][HDn], vs[Cn][HDn];
    __shared__ float sc[Cn][Cn + 1];
    int tid = threadIdx.x;  // 256

    // load q/k/v slices: 32*64/4 = 512 float4 each
    for (int i = tid; i < Cn * HDn / 4; i += 256) {
        int c = i / (HDn / 4);
        int d4 = (i % (HDn / 4)) * 4;
        const float* base = qkv + (size_t)(b * Cn + c) * QKVn + h * HDn + d4;
        *(float4*)&qs[c][d4] = *(const float4*)base;
        *(float4*)&ks[c][d4] = *(const float4*)(base + Rn);
        *(float4*)&vs[c][d4] = *(const float4*)(base + 2 * Rn);
    }
    __syncthreads();

    // scores
    for (int i = tid; i < Cn * Cn; i += 256) {
        int q = i / Cn, k = i % Cn;
        float s = 0.f;
        #pragma unroll
        for (int d = 0; d < HDn; d++) s = fmaf(qs[q][d], ks[k][d], s);
        sc[q][k] = s * 0.125f;  // 1/sqrt(64)
    }
    __syncthreads();

    // softmax per query row (32 rows)
    if (tid < Cn) {
        float mx = -1e30f;
        #pragma unroll
        for (int k = 0; k < Cn; k++) mx = fmaxf(mx, sc[tid][k]);
        float sum = 0.f;
        #pragma unroll
        for (int k = 0; k < Cn; k++) { float e = expf(sc[tid][k] - mx); sc[tid][k] = e; sum += e; }
        float inv = 1.f / sum;
        #pragma unroll
        for (int k = 0; k < Cn; k++) sc[tid][k] *= inv;
    }
    __syncthreads();

    // o = attn @ v
    for (int i = tid; i < Cn * HDn; i += 256) {
        int q = i / HDn, d = i % HDn;
        float s = 0.f;
        #pragma unroll
        for (int k = 0; k < Cn; k++) s = fmaf(sc[q][k], vs[k][d], s);
        o[(size_t)(b * Cn + q) * Rn + h * HDn + d] = s;
    }
}

// ---------------- 4) residual add + LayerNorm, one block (256 thr) per row ----------------
__global__ void add_ln_kernel(const float* __restrict__ a, const float* __restrict__ b,
                              const float* __restrict__ g, const float* __restrict__ beta,
                              float* __restrict__ out) {
    int row = blockIdx.x, t = threadIdx.x;
    __shared__ float s1[8], s2[8];
    size_t o = (size_t)row * Rn + t;
    float v = a[o] + b[o];

    float s = v;
    #pragma unroll
    for (int off = 16; off > 0; off >>= 1) s += __shfl_down_sync(0xffffffffu, s, off);
    if ((t & 31) == 0) s1[t >> 5] = s;
    __syncthreads();
    float mean = (s1[0] + s1[1] + s1[2] + s1[3] + s1[4] + s1[5] + s1[6] + s1[7]) * (1.f / Rn);

    float d = v - mean;
    float q = d * d;
    #pragma unroll
    for (int off = 16; off > 0; off >>= 1) q += __shfl_down_sync(0xffffffffu, q, off);
    if ((t & 31) == 0) s2[t >> 5] = q;
    __syncthreads();
    float var = (s2[0] + s2[1] + s2[2] + s2[3] + s2[4] + s2[5] + s2[6] + s2[7]) * (1.f / Rn);

    out[o] = d * rsqrtf(var + 1e-5f) * g[t] + beta[t];
}

// ---------------- 5) head layer 1: h[b, j] = relu(feat . Wc1[j]) ----------------
// grid (B, 4); block = 256 threads (8 warps); each warp: 4 of the 32 j's in this chunk
__global__ void head1_kernel(const float* __restrict__ host_cat,
                             const float* __restrict__ vir,
                             const float* __restrict__ meta,
                             const float* __restrict__ Wc1,
                             const float* __restrict__ bc1) {
    int b = blockIdx.x;
    int jbase = blockIdx.y * 32;
    int lane = threadIdx.x & 31;
    int w = threadIdx.x >> 5;
    const float* xb = g_x2 + (size_t)b * Cn * Rn;  // 8192 contiguous
    const float* hc = host_cat + b * 64;
    const float* vc = vir + b * 32;
    const float* mt = meta + b * 3;

    for (int jj = w; jj < 32; jj += 8) {
        int j = jbase + jj;
        const float* wr = Wc1 + (size_t)j * HEAD_IN;
        float s = 0.f;
        for (int i = lane; i < Cn * Rn; i += 32) s = fmaf(wr[i], xb[i], s);
        for (int i = lane; i < 64; i += 32) s = fmaf(wr[Cn * Rn + i], hc[i], s);
        s = fmaf(wr[Cn * Rn + 64 + lane], vc[lane], s);
        if (lane < 3) s = fmaf(wr[Cn * Rn + 96 + lane], mt[lane], s);
        #pragma unroll
        for (int off = 16; off > 0; off >>= 1) s += __shfl_down_sync(0xffffffffu, s, off);
        if (lane == 0) g_h[b * 128 + j] = fmaxf(s + bc1[j], 0.f);
    }
}

// ---------------- 6) head layer 2: logits[b] = h[b] . Wc2 + bc2 ----------------
__global__ void head2_kernel(const float* __restrict__ Wc2, const float* __restrict__ bc2,
                             float* __restrict__ out) {
    int b = blockIdx.x;
    int t = threadIdx.x;  // 128
    __shared__ float sred[4];
    float v = g_h[b * 128 + t] * Wc2[t];
    #pragma unroll
    for (int off = 16; off > 0; off >>= 1) v += __shfl_down_sync(0xffffffffu, v, off);
    if ((t & 31) == 0) sred[t >> 5] = v;
    __syncthreads();
    if (t == 0) out[b] = sred[0] + sred[1] + sred[2] + sred[3] + bc2[0];
}

// ---------------- launch ----------------
extern "C" void kernel_launch(void* const* d_in, const int* in_sizes, int n_in,
                              void* d_out, int out_size) {
    const float*         embs        = (const float*)d_in[0];
    const int*           indices     = (const int*)d_in[1];
    const int*           mask        = (const int*)d_in[2];     // bool -> int32
    const float*         host_cat    = (const float*)d_in[3];
    const float*         virus_cat   = (const float*)d_in[4];
    const float*         extra_meta  = (const float*)d_in[5];
    const float*         func_weights= (const float*)d_in[6];
    const float*         Wr          = (const float*)d_in[7];
    const float*         br          = (const float*)d_in[8];
    const float*         Wqkv        = (const float*)d_in[9];
    const float*         bqkv        = (const float*)d_in[10];
    const float*         Wo          = (const float*)d_in[11];
    const float*         bo          = (const float*)d_in[12];
    const float*         ln1_g       = (const float*)d_in[13];
    const float*         ln1_b       = (const float*)d_in[14];
    const float*         W1          = (const float*)d_in[15];
    const float*         b1          = (const float*)d_in[16];
    const float*         W2          = (const float*)d_in[17];
    const float*         b2          = (const float*)d_in[18];
    const float*         ln2_g       = (const float*)d_in[19];
    const float*         ln2_b       = (const float*)d_in[20];
    const float*         Wc1         = (const float*)d_in[21];
    const float*         bc1         = (const float*)d_in[22];
    const float*         Wc2         = (const float*)d_in[23];
    const float*         bc2         = (const float*)d_in[24];
    float* out = (float*)d_out;

    float *agg, *x0, *qkv, *att, *oproj, *x1, *ff1, *ff2, *x2;
    cudaGetSymbolAddress((void**)&agg,   g_agg);
    cudaGetSymbolAddress((void**)&x0,    g_x0);
    cudaGetSymbolAddress((void**)&qkv,   g_qkv);
    cudaGetSymbolAddress((void**)&att,   g_att);
    cudaGetSymbolAddress((void**)&oproj, g_oproj);
    cudaGetSymbolAddress((void**)&x1,    g_x1);
    cudaGetSymbolAddress((void**)&ff1,   g_ff1);
    cudaGetSymbolAddress((void**)&ff2,   g_ff2);
    cudaGetSymbolAddress((void**)&x2,    g_x2);

    // 1) ragged aggregation
    agg_kernel<<<BC, En / 4>>>(embs, indices, mask, func_weights);

    // 2) x0 = agg @ Wr^T + br      [1024, 1280] x [256, 1280]^T
    gemm_kernel<32, 64, 2, 4, false><<<dim3(Rn / 64, BC / 32), 256>>>(agg, Wr, br, x0, BC, Rn, En);

    // 3) qkv = x0 @ Wqkv^T + bqkv  [1024, 256] x [768, 256]^T
    gemm_kernel<64, 64, 4, 4, false><<<dim3(QKVn / 64, BC / 64), 256>>>(x0, Wqkv, bqkv, qkv, BC, QKVn, Rn);

    // 4) attention
    attn_kernel<<<Bn * Hn, 256>>>(qkv, att);

    // 5) oproj = att @ Wo^T + bo
    gemm_kernel<32, 64, 2, 4, false><<<dim3(Rn / 64, BC / 32), 256>>>(att, Wo, bo, oproj, BC, Rn, Rn);

    // 6) x1 = LN(x0 + oproj)
    add_ln_kernel<<<BC, Rn>>>(x0, oproj, ln1_g, ln1_b, x1);

    // 7) ff1 = relu(x1 @ W1^T + b1)   [1024,256] x [512,256]^T
    gemm_kernel<64, 64, 4, 4, true><<<dim3(FFn / 64, BC / 64), 256>>>(x1, W1, b1, ff1, BC, FFn, Rn);

    // 8) ff2 = ff1 @ W2^T + b2        [1024,512] x [256,512]^T
    gemm_kernel<32, 64, 2, 4, false><<<dim3(Rn / 64, BC / 32), 256>>>(ff1, W2, b2, ff2, BC, Rn, FFn);

    // 9) x2 = LN(x1 + ff2)
    add_ln_kernel<<<BC, Rn>>>(x1, ff2, ln2_g, ln2_b, x2);

    // 10) classification head
    head1_kernel<<<dim3(Bn, 4), 256>>>(host_cat, virus_cat, extra_meta, Wc1, bc1);
    head2_kernel<<<Bn, 128>>>(Wc2, bc2, out);
}

// round 4
// speedup vs baseline: 1.2566x; 1.2566x over previous
#include <cuda_runtime.h>
#include <math.h>

// ---------------- problem constants ----------------
static constexpr int Bn = 32, Cn = 32, Sn = 16, En = 1280, Rn = 256;
static constexpr int Hn = 4, HDn = 64, FFn = 512;
static constexpr int BC = Bn * Cn;               // 1024 tokens
static constexpr int HEAD_IN = Cn * Rn + 64 + 32 + 3;  // 8291
static constexpr int QKVn = 3 * Rn;              // 768

// ---------------- scratch (device globals; no allocation allowed) ----------------
__device__ __align__(16) float g_agg[BC * En];
__device__ __align__(16) float g_x0p[4 * BC * Rn];   // split-K partials for x0
__device__ __align__(16) float g_x0[BC * Rn];
__device__ __align__(16) float g_qkv[BC * QKVn];
__device__ __align__(16) float g_att[BC * Rn];
__device__ __align__(16) float g_op[2 * BC * Rn];    // split-K partials for oproj
__device__ __align__(16) float g_x1[BC * Rn];
__device__ __align__(16) float g_ff1[BC * FFn];
__device__ __align__(16) float g_fp[2 * BC * Rn];    // split-K partials for ff2
__device__ __align__(16) float g_x2[BC * Rn];
__device__ __align__(16) float g_h[Bn * 128];

// ---------------- 1) ragged softmax aggregation -> agg[BC, E] ----------------
__global__ void agg_kernel(const float* __restrict__ embs,
                           const int* __restrict__ idx,
                           const int* __restrict__ mask,   // bool -> int32 in harness
                           const float* __restrict__ fw) {
    int bc = blockIdx.x;
    __shared__ float attn[Sn];
    int t = threadIdx.x;
    if (t == 0) {
        float w[Sn];
        int any = 0;
        #pragma unroll
        for (int s = 0; s < Sn; s++) {
            int m = mask[bc * Sn + s];
            any |= m;
            w[s] = m ? fw[idx[bc * Sn + s]] : -1e30f;
        }
        float mx = -1e30f;
        #pragma unroll
        for (int s = 0; s < Sn; s++) mx = fmaxf(mx, w[s]);
        float e[Sn], sum = 0.f;
        #pragma unroll
        for (int s = 0; s < Sn; s++) { e[s] = expf(w[s] - mx); sum += e[s]; }
        float inv = any ? (1.f / sum) : 0.f;
        #pragma unroll
        for (int s = 0; s < Sn; s++) attn[s] = e[s] * inv;
    }
    __syncthreads();
    const float4* ebase = (const float4*)(embs + (size_t)bc * Sn * En);
    float4 acc = make_float4(0.f, 0.f, 0.f, 0.f);
    #pragma unroll
    for (int s = 0; s < Sn; s++) {
        float a = attn[s];
        float4 v = ebase[s * (En / 4) + t];
        acc.x = fmaf(a, v.x, acc.x);
        acc.y = fmaf(a, v.y, acc.y);
        acc.z = fmaf(a, v.z, acc.z);
        acc.w = fmaf(a, v.w, acc.w);
    }
    ((float4*)(g_agg + (size_t)bc * En))[t] = acc;
}

// ---------------- register-blocked fp32 GEMM: C[M,N] = A[M,K] @ B[N,K]^T ----------------
// BM=64, BN=64, BK=16, TM=8, TN=4 -> 128 threads, transposed smem, double-buffered.
// SPLIT: blockIdx.z picks K-slice of length KS; partial written to C + z*M*N (no bias).
template <int BM, int BN, int BK, int TM, int TN, bool RELU, bool SPLIT>
__global__ __launch_bounds__((BM / TM) * (BN / TN))
void gemm_kernel(const float* __restrict__ A,
                 const float* __restrict__ B,
                 const float* __restrict__ bias,
                 float* __restrict__ C,
                 int M, int N, int K, int KS) {
    constexpr int TX = BN / TN;               // 16
    constexpr int THREADS = (BM / TM) * TX;   // 128
    constexpr int NLD = (BM * BK) / (4 * THREADS);  // 2
    __shared__ float As[2][BK][BM];
    __shared__ float Bs[2][BK][BN];

    const int tid = threadIdx.x;
    const int bn0 = blockIdx.x * BN;
    const int bm0 = blockIdx.y * BM;
    const int tx = tid % TX;
    const int ty = tid / TX;

    const int kz   = SPLIT ? blockIdx.z : 0;
    const int k0s  = kz * KS;
    const int klen = SPLIT ? KS : K;
    const int ntiles = klen / BK;
    float* Cout = SPLIT ? C + (size_t)kz * M * N : C;

    float acc[TM][TN];
    #pragma unroll
    for (int i = 0; i < TM; i++)
        #pragma unroll
        for (int j = 0; j < TN; j++) acc[i][j] = 0.f;

    // preload tile 0 directly to smem
    {
        #pragma unroll
        for (int it = 0; it < NLD; it++) {
            int f = tid + it * THREADS;
            int row = f / (BK / 4), c4 = f % (BK / 4);
            float4 v = *(const float4*)&A[(size_t)(bm0 + row) * K + k0s + c4 * 4];
            As[0][c4 * 4 + 0][row] = v.x; As[0][c4 * 4 + 1][row] = v.y;
            As[0][c4 * 4 + 2][row] = v.z; As[0][c4 * 4 + 3][row] = v.w;
        }
        #pragma unroll
        for (int it = 0; it < NLD; it++) {
            int f = tid + it * THREADS;
            int row = f / (BK / 4), c4 = f % (BK / 4);
            float4 v = *(const float4*)&B[(size_t)(bn0 + row) * K + k0s + c4 * 4];
            Bs[0][c4 * 4 + 0][row] = v.x; Bs[0][c4 * 4 + 1][row] = v.y;
            Bs[0][c4 * 4 + 2][row] = v.z; Bs[0][c4 * 4 + 3][row] = v.w;
        }
    }
    __syncthreads();

    int p = 0;
    for (int t = 0; t < ntiles; t++) {
        float4 pa[NLD], pb[NLD];
        const bool has = (t + 1) < ntiles;
        if (has) {
            int kn = k0s + (t + 1) * BK;
            #pragma unroll
            for (int it = 0; it < NLD; it++) {
                int f = tid + it * THREADS;
                int row = f / (BK / 4), c4 = f % (BK / 4);
                pa[it] = *(const float4*)&A[(size_t)(bm0 + row) * K + kn + c4 * 4];
                pb[it] = *(const float4*)&B[(size_t)(bn0 + row) * K + kn + c4 * 4];
            }
        }
        #pragma unroll
        for (int kk = 0; kk < BK; kk++) {
            float a[TM], b[TN];
            #pragma unroll
            for (int i = 0; i < TM; i += 4)
                *(float4*)&a[i] = *(const float4*)&As[p][kk][ty * TM + i];
            #pragma unroll
            for (int j = 0; j < TN; j += 4)
                *(float4*)&b[j] = *(const float4*)&Bs[p][kk][tx * TN + j];
            #pragma unroll
            for (int i = 0; i < TM; i++)
                #pragma unroll
                for (int j = 0; j < TN; j++) acc[i][j] = fmaf(a[i], b[j], acc[i][j]);
        }
        if (has) {
            int q = 1 - p;
            #pragma unroll
            for (int it = 0; it < NLD; it++) {
                int f = tid + it * THREADS;
                int row = f / (BK / 4), c4 = f % (BK / 4);
                As[q][c4 * 4 + 0][row] = pa[it].x; As[q][c4 * 4 + 1][row] = pa[it].y;
                As[q][c4 * 4 + 2][row] = pa[it].z; As[q][c4 * 4 + 3][row] = pa[it].w;
                Bs[q][c4 * 4 + 0][row] = pb[it].x; Bs[q][c4 * 4 + 1][row] = pb[it].y;
                Bs[q][c4 * 4 + 2][row] = pb[it].z; Bs[q][c4 * 4 + 3][row] = pb[it].w;
            }
        }
        __syncthreads();
        p ^= 1;
    }

    #pragma unroll
    for (int i = 0; i < TM; i++) {
        int m = bm0 + ty * TM + i;
        float4 o;
        float* po = &o.x;
        #pragma unroll
        for (int j = 0; j < TN; j++) {
            float v = acc[i][j];
            if (!SPLIT) v += bias[bn0 + tx * TN + j];
            if (RELU) v = fmaxf(v, 0.f);
            po[j] = v;
        }
        *(float4*)&Cout[(size_t)m * N + bn0 + tx * TN] = o;
    }
}

// ---------------- reduce 4 split-K partials + bias -> x0 ----------------
__global__ void reduce4_bias_kernel(const float* __restrict__ p,
                                    const float* __restrict__ bias,
                                    float* __restrict__ out) {
    constexpr int S = BC * Rn;
    int i = blockIdx.x * blockDim.x + threadIdx.x;   // float4 index, S/4 total
    float4 a = ((const float4*)p)[i];
    float4 b = ((const float4*)p)[S / 4 + i];
    float4 c = ((const float4*)p)[2 * S / 4 + i];
    float4 d = ((const float4*)p)[3 * S / 4 + i];
    float4 bb = ((const float4*)bias)[i % (Rn / 4)];
    float4 o;
    o.x = a.x + b.x + c.x + d.x + bb.x;
    o.y = a.y + b.y + c.y + d.y + bb.y;
    o.z = a.z + b.z + c.z + d.z + bb.z;
    o.w = a.w + b.w + c.w + d.w + bb.w;
    ((float4*)out)[i] = o;
}

// ---------------- attention: one block per (b, h) ----------------
__global__ void attn_kernel(const float* __restrict__ qkv, float* __restrict__ o) {
    int b = blockIdx.x / Hn;
    int h = blockIdx.x % Hn;
    __shared__ float qs[Cn][HDn], ks[Cn][HDn], vs[Cn][HDn];
    __shared__ float sc[Cn][Cn + 1];
    int tid = threadIdx.x;  // 256

    for (int i = tid; i < Cn * HDn / 4; i += 256) {
        int c = i / (HDn / 4);
        int d4 = (i % (HDn / 4)) * 4;
        const float* base = qkv + (size_t)(b * Cn + c) * QKVn + h * HDn + d4;
        *(float4*)&qs[c][d4] = *(const float4*)base;
        *(float4*)&ks[c][d4] = *(const float4*)(base + Rn);
        *(float4*)&vs[c][d4] = *(const float4*)(base + 2 * Rn);
    }
    __syncthreads();

    for (int i = tid; i < Cn * Cn; i += 256) {
        int q = i / Cn, k = i % Cn;
        float s = 0.f;
        #pragma unroll
        for (int d = 0; d < HDn; d++) s = fmaf(qs[q][d], ks[k][d], s);
        sc[q][k] = s * 0.125f;
    }
    __syncthreads();

    if (tid < Cn) {
        float mx = -1e30f;
        #pragma unroll
        for (int k = 0; k < Cn; k++) mx = fmaxf(mx, sc[tid][k]);
        float sum = 0.f;
        #pragma unroll
        for (int k = 0; k < Cn; k++) { float e = expf(sc[tid][k] - mx); sc[tid][k] = e; sum += e; }
        float inv = 1.f / sum;
        #pragma unroll
        for (int k = 0; k < Cn; k++) sc[tid][k] *= inv;
    }
    __syncthreads();

    for (int i = tid; i < Cn * HDn; i += 256) {
        int q = i / HDn, d = i % HDn;
        float s = 0.f;
        #pragma unroll
        for (int k = 0; k < Cn; k++) s = fmaf(sc[q][k], vs[k][d], s);
        o[(size_t)(b * Cn + q) * Rn + h * HDn + d] = s;
    }
}

// ---------------- residual + 2 split-K partials + bias, then LayerNorm ----------------
// one block (256 thr) per row;  v = a + p[o] + p[S+o] + bias[col]
__global__ void add_ln_kernel(const float* __restrict__ a, const float* __restrict__ p,
                              const float* __restrict__ bias,
                              const float* __restrict__ g, const float* __restrict__ beta,
                              float* __restrict__ out) {
    constexpr int S = BC * Rn;
    int row = blockIdx.x, t = threadIdx.x;
    __shared__ float s1[8], s2[8];
    size_t o = (size_t)row * Rn + t;
    float v = a[o] + p[o] + p[S + o] + bias[t];

    float s = v;
    #pragma unroll
    for (int off = 16; off > 0; off >>= 1) s += __shfl_down_sync(0xffffffffu, s, off);
    if ((t & 31) == 0) s1[t >> 5] = s;
    __syncthreads();
    float mean = (s1[0] + s1[1] + s1[2] + s1[3] + s1[4] + s1[5] + s1[6] + s1[7]) * (1.f / Rn);

    float d = v - mean;
    float q = d * d;
    #pragma unroll
    for (int off = 16; off > 0; off >>= 1) q += __shfl_down_sync(0xffffffffu, q, off);
    if ((t & 31) == 0) s2[t >> 5] = q;
    __syncthreads();
    float var = (s2[0] + s2[1] + s2[2] + s2[3] + s2[4] + s2[5] + s2[6] + s2[7]) * (1.f / Rn);

    out[o] = d * rsqrtf(var + 1e-5f) * g[t] + beta[t];
}

// ---------------- head layer 1 ----------------
__global__ void head1_kernel(const float* __restrict__ host_cat,
                             const float* __restrict__ vir,
                             const float* __restrict__ meta,
                             const float* __restrict__ Wc1,
                             const float* __restrict__ bc1) {
    int b = blockIdx.x;
    int jbase = blockIdx.y * 32;
    int lane = threadIdx.x & 31;
    int w = threadIdx.x >> 5;
    const float* xb = g_x2 + (size_t)b * Cn * Rn;
    const float* hc = host_cat + b * 64;
    const float* vc = vir + b * 32;
    const float* mt = meta + b * 3;

    for (int jj = w; jj < 32; jj += 8) {
        int j = jbase + jj;
        const float* wr = Wc1 + (size_t)j * HEAD_IN;
        float s = 0.f;
        for (int i = lane; i < Cn * Rn; i += 32) s = fmaf(wr[i], xb[i], s);
        for (int i = lane; i < 64; i += 32) s = fmaf(wr[Cn * Rn + i], hc[i], s);
        s = fmaf(wr[Cn * Rn + 64 + lane], vc[lane], s);
        if (lane < 3) s = fmaf(wr[Cn * Rn + 96 + lane], mt[lane], s);
        #pragma unroll
        for (int off = 16; off > 0; off >>= 1) s += __shfl_down_sync(0xffffffffu, s, off);
        if (lane == 0) g_h[b * 128 + j] = fmaxf(s + bc1[j], 0.f);
    }
}

// ---------------- head layer 2 ----------------
__global__ void head2_kernel(const float* __restrict__ Wc2, const float* __restrict__ bc2,
                             float* __restrict__ out) {
    int b = blockIdx.x;
    int t = threadIdx.x;  // 128
    __shared__ float sred[4];
    float v = g_h[b * 128 + t] * Wc2[t];
    #pragma unroll
    for (int off = 16; off > 0; off >>= 1) v += __shfl_down_sync(0xffffffffu, v, off);
    if ((t & 31) == 0) sred[t >> 5] = v;
    __syncthreads();
    if (t == 0) out[b] = sred[0] + sred[1] + sred[2] + sred[3] + bc2[0];
}

// ---------------- launch ----------------
extern "C" void kernel_launch(void* const* d_in, const int* in_sizes, int n_in,
                              void* d_out, int out_size) {
    const float*         embs        = (const float*)d_in[0];
    const int*           indices     = (const int*)d_in[1];
    const int*           mask        = (const int*)d_in[2];     // bool -> int32
    const float*         host_cat    = (const float*)d_in[3];
    const float*         virus_cat   = (const float*)d_in[4];
    const float*         extra_meta  = (const float*)d_in[5];
    const float*         func_weights= (const float*)d_in[6];
    const float*         Wr          = (const float*)d_in[7];
    const float*         br          = (const float*)d_in[8];
    const float*         Wqkv        = (const float*)d_in[9];
    const float*         bqkv        = (const float*)d_in[10];
    const float*         Wo          = (const float*)d_in[11];
    const float*         bo          = (const float*)d_in[12];
    const float*         ln1_g       = (const float*)d_in[13];
    const float*         ln1_b       = (const float*)d_in[14];
    const float*         W1          = (const float*)d_in[15];
    const float*         b1          = (const float*)d_in[16];
    const float*         W2          = (const float*)d_in[17];
    const float*         b2          = (const float*)d_in[18];
    const float*         ln2_g       = (const float*)d_in[19];
    const float*         ln2_b       = (const float*)d_in[20];
    const float*         Wc1         = (const float*)d_in[21];
    const float*         bc1         = (const float*)d_in[22];
    const float*         Wc2         = (const float*)d_in[23];
    const float*         bc2         = (const float*)d_in[24];
    float* out = (float*)d_out;

    float *agg, *x0p, *x0, *qkv, *att, *op, *x1, *ff1, *fp, *x2;
    cudaGetSymbolAddress((void**)&agg, g_agg);
    cudaGetSymbolAddress((void**)&x0p, g_x0p);
    cudaGetSymbolAddress((void**)&x0,  g_x0);
    cudaGetSymbolAddress((void**)&qkv, g_qkv);
    cudaGetSymbolAddress((void**)&att, g_att);
    cudaGetSymbolAddress((void**)&op,  g_op);
    cudaGetSymbolAddress((void**)&x1,  g_x1);
    cudaGetSymbolAddress((void**)&ff1, g_ff1);
    cudaGetSymbolAddress((void**)&fp,  g_fp);
    cudaGetSymbolAddress((void**)&x2,  g_x2);

    // 1) ragged aggregation
    agg_kernel<<<BC, En / 4>>>(embs, indices, mask, func_weights);

    // 2) x0 partials = agg @ Wr^T  (split-K = 4, 1280/4 = 320)
    gemm_kernel<64, 64, 16, 8, 4, false, true>
        <<<dim3(Rn / 64, BC / 64, 4), 128>>>(agg, Wr, nullptr, x0p, BC, Rn, En, 320);

    // 3) x0 = sum partials + br
    reduce4_bias_kernel<<<(BC * Rn / 4) / 256, 256>>>(x0p, br, x0);

    // 4) qkv = x0 @ Wqkv^T + bqkv
    gemm_kernel<64, 64, 16, 8, 4, false, false>
        <<<dim3(QKVn / 64, BC / 64), 128>>>(x0, Wqkv, bqkv, qkv, BC, QKVn, Rn, 0);

    // 5) attention
    attn_kernel<<<Bn * Hn, 256>>>(qkv, att);

    // 6) oproj partials = att @ Wo^T (split-K = 2, 256/2 = 128)
    gemm_kernel<64, 64, 16, 8, 4, false, true>
        <<<dim3(Rn / 64, BC / 64, 2), 128>>>(att, Wo, nullptr, op, BC, Rn, Rn, 128);

    // 7) x1 = LN(x0 + op0 + op1 + bo)
    add_ln_kernel<<<BC, Rn>>>(x0, op, bo, ln1_g, ln1_b, x1);

    // 8) ff1 = relu(x1 @ W1^T + b1)
    gemm_kernel<64, 64, 16, 8, 4, true, false>
        <<<dim3(FFn / 64, BC / 64), 128>>>(x1, W1, b1, ff1, BC, FFn, Rn, 0);

    // 9) ff2 partials = ff1 @ W2^T (split-K = 2, 512/2 = 256)
    gemm_kernel<64, 64, 16, 8, 4, false, true>
        <<<dim3(Rn / 64, BC / 64, 2), 128>>>(ff1, W2, nullptr, fp, BC, Rn, FFn, 256);

    // 10) x2 = LN(x1 + fp0 + fp1 + b2)
    add_ln_kernel<<<BC, Rn>>>(x1, fp, b2, ln2_g, ln2_b, x2);

    // 11) classification head
    head1_kernel<<<dim3(Bn, 4), 256>>>(host_cat, virus_cat, extra_meta, Wc1, bc1);
    head2_kernel<<<Bn, 128>>>(Wc2, bc2, out);
}

// round 5
// speedup vs baseline: 1.2950x; 1.0306x over previous
#include <cuda_runtime.h>
#include <math.h>

// ---------------- problem constants ----------------
static constexpr int Bn = 32, Cn = 32, Sn = 16, En = 1280, Rn = 256;
static constexpr int Hn = 4, HDn = 64, FFn = 512;
static constexpr int BC = Bn * Cn;               // 1024 tokens
static constexpr int HEAD_IN = Cn * Rn + 64 + 32 + 3;  // 8291
static constexpr int QKVn = 3 * Rn;              // 768

// ---------------- scratch (device globals; no allocation allowed) ----------------
__device__ __align__(16) float g_agg[BC * En];
__device__ __align__(16) float g_x0p[4 * BC * Rn];    // x0 split-K partials
__device__ __align__(16) float g_qkvp[4 * BC * QKVn]; // qkv split-K partials
__device__ __align__(16) float g_att[BC * Rn];
__device__ __align__(16) float g_opp[4 * BC * Rn];    // oproj partials
__device__ __align__(16) float g_x1[BC * Rn];
__device__ __align__(16) float g_ff1p[4 * BC * FFn];  // ff1 partials
__device__ __align__(16) float g_fpp[4 * BC * Rn];    // ff2 partials
__device__ __align__(16) float g_x2[BC * Rn];
__device__ __align__(16) float g_h[Bn * 128];

// ---------------- helpers ----------------
__device__ __forceinline__ float4 sum4f4(const float* __restrict__ p, size_t idx, size_t S,
                                         const float* __restrict__ bias, int bidx) {
    float4 a = *(const float4*)(p + idx);
    float4 b = *(const float4*)(p + S + idx);
    float4 c = *(const float4*)(p + 2 * S + idx);
    float4 d = *(const float4*)(p + 3 * S + idx);
    float4 bb = *(const float4*)(bias + bidx);
    a.x += b.x + c.x + d.x + bb.x;
    a.y += b.y + c.y + d.y + bb.y;
    a.z += b.z + c.z + d.z + bb.z;
    a.w += b.w + c.w + d.w + bb.w;
    return a;
}

// APRE: 0 = plain A; 1 = A is 4 split-K partials + abias; 2 = relu of (1)
template <int APRE>
__device__ __forceinline__ float4 loadA4(const float* __restrict__ A,
                                         const float* __restrict__ ab,
                                         size_t idx, int k, size_t SA) {
    if (APRE == 0) return *(const float4*)(A + idx);
    float4 v = sum4f4(A, idx, SA, ab, k);
    if (APRE == 2) {
        v.x = fmaxf(v.x, 0.f); v.y = fmaxf(v.y, 0.f);
        v.z = fmaxf(v.z, 0.f); v.w = fmaxf(v.w, 0.f);
    }
    return v;
}

// ---------------- 1) ragged softmax aggregation -> agg[BC, E] ----------------
__global__ void agg_kernel(const float* __restrict__ embs,
                           const int* __restrict__ idx,
                           const int* __restrict__ mask,   // bool -> int32 in harness
                           const float* __restrict__ fw) {
    int bc = blockIdx.x;
    __shared__ float attn[Sn];
    int t = threadIdx.x;
    if (t == 0) {
        float w[Sn];
        int any = 0;
        #pragma unroll
        for (int s = 0; s < Sn; s++) {
            int m = mask[bc * Sn + s];
            any |= m;
            w[s] = m ? fw[idx[bc * Sn + s]] : -1e30f;
        }
        float mx = -1e30f;
        #pragma unroll
        for (int s = 0; s < Sn; s++) mx = fmaxf(mx, w[s]);
        float e[Sn], sum = 0.f;
        #pragma unroll
        for (int s = 0; s < Sn; s++) { e[s] = expf(w[s] - mx); sum += e[s]; }
        float inv = any ? (1.f / sum) : 0.f;
        #pragma unroll
        for (int s = 0; s < Sn; s++) attn[s] = e[s] * inv;
    }
    __syncthreads();
    const float4* ebase = (const float4*)(embs + (size_t)bc * Sn * En);
    float4 acc = make_float4(0.f, 0.f, 0.f, 0.f);
    #pragma unroll
    for (int s = 0; s < Sn; s++) {
        float a = attn[s];
        float4 v = ebase[s * (En / 4) + t];
        acc.x = fmaf(a, v.x, acc.x);
        acc.y = fmaf(a, v.y, acc.y);
        acc.z = fmaf(a, v.z, acc.z);
        acc.w = fmaf(a, v.w, acc.w);
    }
    ((float4*)(g_agg + (size_t)bc * En))[t] = acc;
}

// ---------------- register-blocked fp32 GEMM: C[M,N](partial) = A[M,K] @ B[N,K]^T ----------------
// BM=BN=64, BK=16, TM=8, TN=4 -> 128 threads, transposed smem, double-buffered.
// Always split-K: blockIdx.z picks K-slice of length KS; partial -> C + z*M*N.
template <int BM, int BN, int BK, int TM, int TN, int APRE>
__global__ __launch_bounds__((BM / TM) * (BN / TN))
void gemm_kernel(const float* __restrict__ A,
                 const float* __restrict__ abias,
                 const float* __restrict__ B,
                 float* __restrict__ C,
                 int M, int N, int K, int KS, size_t SA) {
    constexpr int TX = BN / TN;               // 16
    constexpr int THREADS = (BM / TM) * TX;   // 128
    constexpr int NLD = (BM * BK) / (4 * THREADS);  // 2
    __shared__ float As[2][BK][BM];
    __shared__ float Bs[2][BK][BN];

    const int tid = threadIdx.x;
    const int bn0 = blockIdx.x * BN;
    const int bm0 = blockIdx.y * BM;
    const int tx = tid % TX;
    const int ty = tid / TX;

    const int kz   = blockIdx.z;
    const int k0s  = kz * KS;
    const int ntiles = KS / BK;
    float* Cout = C + (size_t)kz * M * N;

    float acc[TM][TN];
    #pragma unroll
    for (int i = 0; i < TM; i++)
        #pragma unroll
        for (int j = 0; j < TN; j++) acc[i][j] = 0.f;

    // preload tile 0
    {
        #pragma unroll
        for (int it = 0; it < NLD; it++) {
            int f = tid + it * THREADS;
            int row = f / (BK / 4), c4 = f % (BK / 4);
            int kcol = k0s + c4 * 4;
            float4 v = loadA4<APRE>(A, abias, (size_t)(bm0 + row) * K + kcol, kcol, SA);
            As[0][c4 * 4 + 0][row] = v.x; As[0][c4 * 4 + 1][row] = v.y;
            As[0][c4 * 4 + 2][row] = v.z; As[0][c4 * 4 + 3][row] = v.w;
        }
        #pragma unroll
        for (int it = 0; it < NLD; it++) {
            int f = tid + it * THREADS;
            int row = f / (BK / 4), c4 = f % (BK / 4);
            float4 v = *(const float4*)&B[(size_t)(bn0 + row) * K + k0s + c4 * 4];
            Bs[0][c4 * 4 + 0][row] = v.x; Bs[0][c4 * 4 + 1][row] = v.y;
            Bs[0][c4 * 4 + 2][row] = v.z; Bs[0][c4 * 4 + 3][row] = v.w;
        }
    }
    __syncthreads();

    int p = 0;
    for (int t = 0; t < ntiles; t++) {
        float4 pa[NLD], pb[NLD];
        const bool has = (t + 1) < ntiles;
        if (has) {
            int kn = k0s + (t + 1) * BK;
            #pragma unroll
            for (int it = 0; it < NLD; it++) {
                int f = tid + it * THREADS;
                int row = f / (BK / 4), c4 = f % (BK / 4);
                int kcol = kn + c4 * 4;
                pa[it] = loadA4<APRE>(A, abias, (size_t)(bm0 + row) * K + kcol, kcol, SA);
                pb[it] = *(const float4*)&B[(size_t)(bn0 + row) * K + kcol];
            }
        }
        #pragma unroll
        for (int kk = 0; kk < BK; kk++) {
            float a[TM], b[TN];
            #pragma unroll
            for (int i = 0; i < TM; i += 4)
                *(float4*)&a[i] = *(const float4*)&As[p][kk][ty * TM + i];
            #pragma unroll
            for (int j = 0; j < TN; j += 4)
                *(float4*)&b[j] = *(const float4*)&Bs[p][kk][tx * TN + j];
            #pragma unroll
            for (int i = 0; i < TM; i++)
                #pragma unroll
                for (int j = 0; j < TN; j++) acc[i][j] = fmaf(a[i], b[j], acc[i][j]);
        }
        if (has) {
            int q = 1 - p;
            #pragma unroll
            for (int it = 0; it < NLD; it++) {
                int f = tid + it * THREADS;
                int row = f / (BK / 4), c4 = f % (BK / 4);
                As[q][c4 * 4 + 0][row] = pa[it].x; As[q][c4 * 4 + 1][row] = pa[it].y;
                As[q][c4 * 4 + 2][row] = pa[it].z; As[q][c4 * 4 + 3][row] = pa[it].w;
                Bs[q][c4 * 4 + 0][row] = pb[it].x; Bs[q][c4 * 4 + 1][row] = pb[it].y;
                Bs[q][c4 * 4 + 2][row] = pb[it].z; Bs[q][c4 * 4 + 3][row] = pb[it].w;
            }
        }
        __syncthreads();
        p ^= 1;
    }

    #pragma unroll
    for (int i = 0; i < TM; i++) {
        int m = bm0 + ty * TM + i;
        float4 o = make_float4(acc[i][0], acc[i][1], acc[i][2], acc[i][3]);
        *(float4*)&Cout[(size_t)m * N + bn0 + tx * TN] = o;
    }
}

// ---------------- attention: one block per (b, h, query-half) ----------------
// qkv comes in as 4 split-K partials + bias; summed while staging to smem.
__global__ void attn_kernel(const float* __restrict__ qkvp,
                            const float* __restrict__ bqkv,
                            float* __restrict__ o) {
    constexpr size_t SQ = (size_t)BC * QKVn;
    int b = blockIdx.x / Hn;
    int h = blockIdx.x % Hn;
    int q0 = blockIdx.y * 16;
    __shared__ float qs[16][HDn], ks[Cn][HDn], vs[Cn][HDn];
    __shared__ float sc[16][Cn + 1];
    int tid = threadIdx.x;  // 256

    // load k, v: 32 rows x 16 float4 = 512 each -> 2 per thread
    for (int i = tid; i < Cn * (HDn / 4); i += 256) {
        int c = i / (HDn / 4);
        int d4 = (i % (HDn / 4)) * 4;
        size_t base = (size_t)(b * Cn + c) * QKVn + h * HDn + d4;
        float4 kv = sum4f4(qkvp, base + Rn, SQ, bqkv, Rn + h * HDn + d4);
        float4 vv = sum4f4(qkvp, base + 2 * Rn, SQ, bqkv, 2 * Rn + h * HDn + d4);
        *(float4*)&ks[c][d4] = kv;
        *(float4*)&vs[c][d4] = vv;
    }
    // load q for this half: 16 rows x 16 float4 = 256 -> 1 per thread
    {
        int c = tid / (HDn / 4);
        int d4 = (tid % (HDn / 4)) * 4;
        size_t base = (size_t)(b * Cn + q0 + c) * QKVn + h * HDn + d4;
        *(float4*)&qs[c][d4] = sum4f4(qkvp, base, SQ, bqkv, h * HDn + d4);
    }
    __syncthreads();

    // scores: 16x32 = 512 -> 2 per thread
    for (int i = tid; i < 16 * Cn; i += 256) {
        int q = i / Cn, k = i % Cn;
        float s = 0.f;
        #pragma unroll
        for (int d = 0; d < HDn; d++) s = fmaf(qs[q][d], ks[k][d], s);
        sc[q][k] = s * 0.125f;
    }
    __syncthreads();

    if (tid < 16) {
        float mx = -1e30f;
        #pragma unroll
        for (int k = 0; k < Cn; k++) mx = fmaxf(mx, sc[tid][k]);
        float sum = 0.f;
        #pragma unroll
        for (int k = 0; k < Cn; k++) { float e = expf(sc[tid][k] - mx); sc[tid][k] = e; sum += e; }
        float inv = 1.f / sum;
        #pragma unroll
        for (int k = 0; k < Cn; k++) sc[tid][k] *= inv;
    }
    __syncthreads();

    // out: 16x64 = 1024 -> 4 per thread
    for (int i = tid; i < 16 * HDn; i += 256) {
        int q = i / HDn, d = i % HDn;
        float s = 0.f;
        #pragma unroll
        for (int k = 0; k < Cn; k++) s = fmaf(sc[q][k], vs[k][d], s);
        o[(size_t)(b * Cn + q0 + q) * Rn + h * HDn + d] = s;
    }
}

// ---------------- residual(+partials) + LayerNorm ----------------
// NA=4: residual = sum of 4 a-partials + abias;  NA=1: residual = a[o] (abias unused)
// p is always 4 partials + pbias.
template <int NA>
__global__ void add_ln_kernel(const float* __restrict__ a, const float* __restrict__ abias,
                              const float* __restrict__ p, const float* __restrict__ pbias,
                              const float* __restrict__ g, const float* __restrict__ beta,
                              float* __restrict__ out) {
    constexpr size_t S = (size_t)BC * Rn;
    int row = blockIdx.x, t = threadIdx.x;
    __shared__ float s1[8], s2[8];
    size_t o = (size_t)row * Rn + t;
    float v;
    if (NA == 4) {
        v = a[o] + a[S + o] + a[2 * S + o] + a[3 * S + o] + abias[t];
    } else {
        v = a[o];
    }
    v += p[o] + p[S + o] + p[2 * S + o] + p[3 * S + o] + pbias[t];

    float s = v;
    #pragma unroll
    for (int off = 16; off > 0; off >>= 1) s += __shfl_down_sync(0xffffffffu, s, off);
    if ((t & 31) == 0) s1[t >> 5] = s;
    __syncthreads();
    float mean = (s1[0] + s1[1] + s1[2] + s1[3] + s1[4] + s1[5] + s1[6] + s1[7]) * (1.f / Rn);

    float d = v - mean;
    float q = d * d;
    #pragma unroll
    for (int off = 16; off > 0; off >>= 1) q += __shfl_down_sync(0xffffffffu, q, off);
    if ((t & 31) == 0) s2[t >> 5] = q;
    __syncthreads();
    float var = (s2[0] + s2[1] + s2[2] + s2[3] + s2[4] + s2[5] + s2[6] + s2[7]) * (1.f / Rn);

    out[o] = d * rsqrtf(var + 1e-5f) * g[t] + beta[t];
}

// ---------------- head layer 1 ----------------
__global__ void head1_kernel(const float* __restrict__ host_cat,
                             const float* __restrict__ vir,
                             const float* __restrict__ meta,
                             const float* __restrict__ Wc1,
                             const float* __restrict__ bc1) {
    int b = blockIdx.x;
    int jbase = blockIdx.y * 32;
    int lane = threadIdx.x & 31;
    int w = threadIdx.x >> 5;
    const float* xb = g_x2 + (size_t)b * Cn * Rn;
    const float* hc = host_cat + b * 64;
    const float* vc = vir + b * 32;
    const float* mt = meta + b * 3;

    for (int jj = w; jj < 32; jj += 8) {
        int j = jbase + jj;
        const float* wr = Wc1 + (size_t)j * HEAD_IN;
        float s = 0.f;
        for (int i = lane; i < Cn * Rn; i += 32) s = fmaf(wr[i], xb[i], s);
        for (int i = lane; i < 64; i += 32) s = fmaf(wr[Cn * Rn + i], hc[i], s);
        s = fmaf(wr[Cn * Rn + 64 + lane], vc[lane], s);
        if (lane < 3) s = fmaf(wr[Cn * Rn + 96 + lane], mt[lane], s);
        #pragma unroll
        for (int off = 16; off > 0; off >>= 1) s += __shfl_down_sync(0xffffffffu, s, off);
        if (lane == 0) g_h[b * 128 + j] = fmaxf(s + bc1[j], 0.f);
    }
}

// ---------------- head layer 2 ----------------
__global__ void head2_kernel(const float* __restrict__ Wc2, const float* __restrict__ bc2,
                             float* __restrict__ out) {
    int b = blockIdx.x;
    int t = threadIdx.x;  // 128
    __shared__ float sred[4];
    float v = g_h[b * 128 + t] * Wc2[t];
    #pragma unroll
    for (int off = 16; off > 0; off >>= 1) v += __shfl_down_sync(0xffffffffu, v, off);
    if ((t & 31) == 0) sred[t >> 5] = v;
    __syncthreads();
    if (t == 0) out[b] = sred[0] + sred[1] + sred[2] + sred[3] + bc2[0];
}

// ---------------- launch ----------------
extern "C" void kernel_launch(void* const* d_in, const int* in_sizes, int n_in,
                              void* d_out, int out_size) {
    const float*         embs        = (const float*)d_in[0];
    const int*           indices     = (const int*)d_in[1];
    const int*           mask        = (const int*)d_in[2];     // bool -> int32
    const float*         host_cat    = (const float*)d_in[3];
    const float*         virus_cat   = (const float*)d_in[4];
    const float*         extra_meta  = (const float*)d_in[5];
    const float*         func_weights= (const float*)d_in[6];
    const float*         Wr          = (const float*)d_in[7];
    const float*         br          = (const float*)d_in[8];
    const float*         Wqkv        = (const float*)d_in[9];
    const float*         bqkv        = (const float*)d_in[10];
    const float*         Wo          = (const float*)d_in[11];
    const float*         bo          = (const float*)d_in[12];
    const float*         ln1_g       = (const float*)d_in[13];
    const float*         ln1_b       = (const float*)d_in[14];
    const float*         W1          = (const float*)d_in[15];
    const float*         b1          = (const float*)d_in[16];
    const float*         W2          = (const float*)d_in[17];
    const float*         b2          = (const float*)d_in[18];
    const float*         ln2_g       = (const float*)d_in[19];
    const float*         ln2_b       = (const float*)d_in[20];
    const float*         Wc1         = (const float*)d_in[21];
    const float*         bc1         = (const float*)d_in[22];
    const float*         Wc2         = (const float*)d_in[23];
    const float*         bc2         = (const float*)d_in[24];
    float* out = (float*)d_out;

    float *agg, *x0p, *qkvp, *att, *opp, *x1, *ff1p, *fpp, *x2;
    cudaGetSymbolAddress((void**)&agg,  g_agg);
    cudaGetSymbolAddress((void**)&x0p,  g_x0p);
    cudaGetSymbolAddress((void**)&qkvp, g_qkvp);
    cudaGetSymbolAddress((void**)&att,  g_att);
    cudaGetSymbolAddress((void**)&opp,  g_opp);
    cudaGetSymbolAddress((void**)&x1,   g_x1);
    cudaGetSymbolAddress((void**)&ff1p, g_ff1p);
    cudaGetSymbolAddress((void**)&fpp,  g_fpp);
    cudaGetSymbolAddress((void**)&x2,   g_x2);

    // 1) ragged aggregation
    agg_kernel<<<BC, En / 4>>>(embs, indices, mask, func_weights);

    // 2) x0 partials = agg @ Wr^T   (split-K=4, KS=320) grid 4x16x4 = 256
    gemm_kernel<64, 64, 16, 8, 4, 0>
        <<<dim3(Rn / 64, BC / 64, 4), 128>>>(agg, nullptr, Wr, x0p, BC, Rn, En, 320, 0);

    // 3) qkv partials = (sum4 x0p + br) @ Wqkv^T  (split-K=4, KS=64) grid 12x16x4 = 768
    gemm_kernel<64, 64, 16, 8, 4, 1>
        <<<dim3(QKVn / 64, BC / 64, 4), 128>>>(x0p, br, Wqkv, qkvp, BC, QKVn, Rn, 64,
                                               (size_t)BC * Rn);

    // 4) attention (sums qkv partials + bias)  grid (128, 2)
    attn_kernel<<<dim3(Bn * Hn, 2), 256>>>(qkvp, bqkv, att);

    // 5) oproj partials = att @ Wo^T  (split-K=4, KS=64) grid 4x16x4 = 256
    gemm_kernel<64, 64, 16, 8, 4, 0>
        <<<dim3(Rn / 64, BC / 64, 4), 128>>>(att, nullptr, Wo, opp, BC, Rn, Rn, 64, 0);

    // 6) x1 = LN(sum4 x0p + br + sum4 opp + bo)
    add_ln_kernel<4><<<BC, Rn>>>(x0p, br, opp, bo, ln1_g, ln1_b, x1);

    // 7) ff1 partials = x1 @ W1^T  (split-K=4, KS=64) grid 8x16x4 = 512
    gemm_kernel<64, 64, 16, 8, 4, 0>
        <<<dim3(FFn / 64, BC / 64, 4), 128>>>(x1, nullptr, W1, ff1p, BC, FFn, Rn, 64, 0);

    // 8) ff2 partials = relu(sum4 ff1p + b1) @ W2^T  (split-K=4, KS=128) grid 4x16x4 = 256
    gemm_kernel<64, 64, 16, 8, 4, 2>
        <<<dim3(Rn / 64, BC / 64, 4), 128>>>(ff1p, b1, W2, fpp, BC, Rn, FFn, 128,
                                             (size_t)BC * FFn);

    // 9) x2 = LN(x1 + sum4 fpp + b2)
    add_ln_kernel<1><<<BC, Rn>>>(x1, nullptr, fpp, b2, ln2_g, ln2_b, x2);

    // 10) classification head
    head1_kernel<<<dim3(Bn, 4), 256>>>(host_cat, virus_cat, extra_meta, Wc1, bc1);
    head2_kernel<<<Bn, 128>>>(Wc2, bc2, out);
}

// round 6
// speedup vs baseline: 1.5141x; 1.1692x over previous
#include <cuda_runtime.h>
#include <math.h>

// ---------------- problem constants ----------------
static constexpr int Bn = 32, Cn = 32, Sn = 16, En = 1280, Rn = 256;
static constexpr int Hn = 4, HDn = 64, FFn = 512;
static constexpr int BC = Bn * Cn;               // 1024 tokens
static constexpr int HEAD_IN = Cn * Rn + 64 + 32 + 3;  // 8291
static constexpr int QKVn = 3 * Rn;              // 768

static constexpr int NBLK = 148;                 // persistent blocks (<= #SMs)
static constexpr int NTHR = 256;                 // threads per block (2 groups of 128)
static constexpr int NGRP = 2 * NBLK;            // 296 worker groups

// ---------------- device scratch ----------------
__device__ float g_aw[BC * Sn];
__device__ __align__(16) float g_agg[BC * En];
__device__ __align__(16) float g_x0p[4 * BC * Rn];    // x0 partials (split 4)
__device__ __align__(16) float g_qkvp[2 * BC * QKVn]; // qkv partials (split 2)
__device__ __align__(16) float g_att[BC * Rn];
__device__ __align__(16) float g_opp[2 * BC * Rn];    // oproj partials (split 2)
__device__ __align__(16) float g_x1[BC * Rn];
__device__ __align__(16) float g_ff1p[2 * BC * FFn];  // ff1 partials (split 2)
__device__ __align__(16) float g_fpp[2 * BC * Rn];    // ff2 partials (split 2)
__device__ __align__(16) float g_x2[BC * Rn];
__device__ __align__(16) float g_h[Bn * 128];
__device__ unsigned g_bar[16];                        // monotonic barrier counters

// ---------------- shared memory (union across phases) ----------------
struct GemmSmem { float As[2][16][64]; float Bs[2][16][64]; };          // 16 KB
struct AttnSmem { float ks[32 * 65]; float vs[32 * 65]; float qs[16 * 65]; float sc[16 * 33]; };
union SmemU {
    GemmSmem g[2];   // 32 KB
    AttnSmem a[2];   // ~45.8 KB
};

// ---------------- grid-wide barrier (monotonic, replay-safe) ----------------
__device__ __forceinline__ void gsync(int k) {
    __syncthreads();
    if (threadIdx.x == 0) {
        __threadfence();
        unsigned old = atomicAdd(&g_bar[k], 1u);
        unsigned target = (old / NBLK + 1u) * NBLK;
        volatile unsigned* p = &g_bar[k];
        while (*p < target) { }
        __threadfence();
    }
    __syncthreads();
}

// group barrier: 128 threads, named barrier id 1 or 2
#define GBAR(id) asm volatile("bar.sync %0, %1;" :: "r"(id), "r"(128) : "memory")

// ---------------- helpers ----------------
template <int NP, bool RELUA>
__device__ __forceinline__ float4 loadPre(const float* __restrict__ A,
                                          const float* __restrict__ ab,
                                          size_t idx, int bcol, size_t SA) {
    float4 v = *(const float4*)(A + idx);
    if (NP >= 2) {
        float4 t = *(const float4*)(A + SA + idx);
        v.x += t.x; v.y += t.y; v.z += t.z; v.w += t.w;
    }
    if (NP >= 4) {
        float4 t = *(const float4*)(A + 2 * SA + idx);
        float4 u = *(const float4*)(A + 3 * SA + idx);
        v.x += t.x + u.x; v.y += t.y + u.y; v.z += t.z + u.z; v.w += t.w + u.w;
    }
    if (NP > 0) {
        float4 bb = *(const float4*)(ab + bcol);
        v.x += bb.x; v.y += bb.y; v.z += bb.z; v.w += bb.w;
        if (RELUA) {
            v.x = fmaxf(v.x, 0.f); v.y = fmaxf(v.y, 0.f);
            v.z = fmaxf(v.z, 0.f); v.w = fmaxf(v.w, 0.f);
        }
    }
    return v;
}

__device__ __forceinline__ float4 sum2b(const float* __restrict__ P, size_t idx, size_t S,
                                        const float* __restrict__ bias, int bi) {
    float4 a = *(const float4*)(P + idx);
    float4 b = *(const float4*)(P + S + idx);
    float4 c = *(const float4*)(bias + bi);
    a.x += b.x + c.x; a.y += b.y + c.y; a.z += b.z + c.z; a.w += b.w + c.w;
    return a;
}

// ---------------- GEMM worker (128-thread group): C(part z) = A[M,K] @ B[N,K]^T ----------------
// tile 64x64, BK=16, TM=8, TN=4; double-buffered; group-strided over tiles.
template <int NP, bool RELUA>
__device__ void gemm_phase(const float* __restrict__ A, const float* __restrict__ ab,
                           const float* __restrict__ B, float* __restrict__ C,
                           int N, int K, int ntn, int nsplit, int KS, size_t SA,
                           float* __restrict__ As, float* __restrict__ Bs,
                           int ltid, int barid, int grp) {
    const int ntiles = ntn * 16 * nsplit;
    const int tx = ltid & 15, ty = ltid >> 4;
    for (int tile = grp; tile < ntiles; tile += NGRP) {
        int z = tile / (ntn * 16);
        int rem = tile - z * (ntn * 16);
        int m = rem / ntn, n = rem - m * ntn;
        int bm0 = m * 64, bn0 = n * 64, k0s = z * KS;

        float acc[8][4];
        #pragma unroll
        for (int i = 0; i < 8; i++)
            #pragma unroll
            for (int j = 0; j < 4; j++) acc[i][j] = 0.f;

        // preload k-tile 0 into buffer 0
        #pragma unroll
        for (int it = 0; it < 2; it++) {
            int f = ltid + it * 128;
            int row = f >> 2, c4 = (f & 3) * 4;
            int kcol = k0s + c4;
            float4 v = loadPre<NP, RELUA>(A, ab, (size_t)(bm0 + row) * K + kcol, kcol, SA);
            As[(c4 + 0) * 64 + row] = v.x; As[(c4 + 1) * 64 + row] = v.y;
            As[(c4 + 2) * 64 + row] = v.z; As[(c4 + 3) * 64 + row] = v.w;
            float4 w = *(const float4*)&B[(size_t)(bn0 + row) * K + kcol];
            Bs[(c4 + 0) * 64 + row] = w.x; Bs[(c4 + 1) * 64 + row] = w.y;
            Bs[(c4 + 2) * 64 + row] = w.z; Bs[(c4 + 3) * 64 + row] = w.w;
        }
        GBAR(barid);

        int p = 0;
        const int nt = KS / 16;
        for (int t = 0; t < nt; t++) {
            float4 pa[2], pb[2];
            const bool has = (t + 1) < nt;
            if (has) {
                int kn = k0s + (t + 1) * 16;
                #pragma unroll
                for (int it = 0; it < 2; it++) {
                    int f = ltid + it * 128;
                    int row = f >> 2, c4 = (f & 3) * 4;
                    int kcol = kn + c4;
                    pa[it] = loadPre<NP, RELUA>(A, ab, (size_t)(bm0 + row) * K + kcol, kcol, SA);
                    pb[it] = *(const float4*)&B[(size_t)(bn0 + row) * K + kcol];
                }
            }
            const float* Ap = As + p * 1024;
            const float* Bp = Bs + p * 1024;
            #pragma unroll
            for (int kk = 0; kk < 16; kk++) {
                float a[8], b[4];
                #pragma unroll
                for (int i = 0; i < 8; i += 4)
                    *(float4*)&a[i] = *(const float4*)&Ap[kk * 64 + ty * 8 + i];
                *(float4*)&b[0] = *(const float4*)&Bp[kk * 64 + tx * 4];
                #pragma unroll
                for (int i = 0; i < 8; i++)
                    #pragma unroll
                    for (int j = 0; j < 4; j++) acc[i][j] = fmaf(a[i], b[j], acc[i][j]);
            }
            if (has) {
                float* Aq = As + (1 - p) * 1024;
                float* Bq = Bs + (1 - p) * 1024;
                #pragma unroll
                for (int it = 0; it < 2; it++) {
                    int f = ltid + it * 128;
                    int row = f >> 2, c4 = (f & 3) * 4;
                    Aq[(c4 + 0) * 64 + row] = pa[it].x; Aq[(c4 + 1) * 64 + row] = pa[it].y;
                    Aq[(c4 + 2) * 64 + row] = pa[it].z; Aq[(c4 + 3) * 64 + row] = pa[it].w;
                    Bq[(c4 + 0) * 64 + row] = pb[it].x; Bq[(c4 + 1) * 64 + row] = pb[it].y;
                    Bq[(c4 + 2) * 64 + row] = pb[it].z; Bq[(c4 + 3) * 64 + row] = pb[it].w;
                }
            }
            GBAR(barid);
            p ^= 1;
        }

        float* Cout = C + (size_t)z * BC * N;
        #pragma unroll
        for (int i = 0; i < 8; i++) {
            float4 o = make_float4(acc[i][0], acc[i][1], acc[i][2], acc[i][3]);
            *(float4*)&Cout[(size_t)(bm0 + ty * 8 + i) * N + bn0 + tx * 4] = o;
        }
    }
}

// ---------------- attention worker (128-thread group) ----------------
// unit = (b, h, qhalf): 16 query rows vs all 32 keys. qkv = sum of 2 partials + bias.
__device__ void attn_phase(AttnSmem* s, const float* __restrict__ bqkv,
                           int ltid, int barid, int grp) {
    constexpr size_t SQ = (size_t)BC * QKVn;
    for (int u = grp; u < Bn * Hn * 2; u += NGRP) {
        int b = u >> 3, h = (u >> 1) & 3, half = u & 1;
        int q0 = half * 16;
        // load k, v: 512 float4 over 128 threads
        #pragma unroll
        for (int it = 0; it < 4; it++) {
            int f = ltid + it * 128;
            int c = f >> 4, d4 = (f & 15) * 4;
            size_t base = (size_t)(b * Cn + c) * QKVn + h * HDn + d4;
            float4 kv = sum2b(g_qkvp, base + Rn, SQ, bqkv, Rn + h * HDn + d4);
            float4 vv = sum2b(g_qkvp, base + 2 * Rn, SQ, bqkv, 2 * Rn + h * HDn + d4);
            s->ks[c * 65 + d4 + 0] = kv.x; s->ks[c * 65 + d4 + 1] = kv.y;
            s->ks[c * 65 + d4 + 2] = kv.z; s->ks[c * 65 + d4 + 3] = kv.w;
            s->vs[c * 65 + d4 + 0] = vv.x; s->vs[c * 65 + d4 + 1] = vv.y;
            s->vs[c * 65 + d4 + 2] = vv.z; s->vs[c * 65 + d4 + 3] = vv.w;
        }
        // load q (16 rows): 256 float4
        #pragma unroll
        for (int it = 0; it < 2; it++) {
            int f = ltid + it * 128;
            int c = f >> 4, d4 = (f & 15) * 4;
            size_t base = (size_t)(b * Cn + q0 + c) * QKVn + h * HDn + d4;
            float4 qv = sum2b(g_qkvp, base, SQ, bqkv, h * HDn + d4);
            s->qs[c * 65 + d4 + 0] = qv.x; s->qs[c * 65 + d4 + 1] = qv.y;
            s->qs[c * 65 + d4 + 2] = qv.z; s->qs[c * 65 + d4 + 3] = qv.w;
        }
        GBAR(barid);
        // scores: 16x32
        #pragma unroll
        for (int r = 0; r < 4; r++) {
            int i = ltid + r * 128;
            int k = i & 31, q = i >> 5;
            float sum = 0.f;
            #pragma unroll
            for (int d = 0; d < HDn; d++) sum = fmaf(s->qs[q * 65 + d], s->ks[k * 65 + d], sum);
            s->sc[q * 33 + k] = sum * 0.125f;
        }
        GBAR(barid);
        if (ltid < 16) {
            float mx = -1e30f;
            #pragma unroll
            for (int k = 0; k < Cn; k++) mx = fmaxf(mx, s->sc[ltid * 33 + k]);
            float sum = 0.f;
            #pragma unroll
            for (int k = 0; k < Cn; k++) {
                float e = expf(s->sc[ltid * 33 + k] - mx);
                s->sc[ltid * 33 + k] = e; sum += e;
            }
            float inv = 1.f / sum;
            #pragma unroll
            for (int k = 0; k < Cn; k++) s->sc[ltid * 33 + k] *= inv;
        }
        GBAR(barid);
        // out: 16x64
        #pragma unroll
        for (int r = 0; r < 8; r++) {
            int i = ltid + r * 128;
            int d = i & 63, q = i >> 6;
            float sum = 0.f;
            #pragma unroll
            for (int k = 0; k < Cn; k++) sum = fmaf(s->sc[q * 33 + k], s->vs[k * 65 + d], sum);
            g_att[(size_t)(b * Cn + q0 + q) * Rn + h * HDn + d] = sum;
        }
        GBAR(barid);   // smem reused by next unit
    }
}

// ---------------- LayerNorm worker: one warp per row ----------------
// NPA=4: residual = sum4(a)+ab ; NPA=1: residual = a. p2 always sum2 + pb.
template <int NPA>
__device__ void ln_phase(const float* __restrict__ a, const float* __restrict__ ab,
                         const float* __restrict__ p2, const float* __restrict__ pb,
                         const float* __restrict__ g, const float* __restrict__ be,
                         float* __restrict__ out) {
    int row = blockIdx.x * 8 + (threadIdx.x >> 5);
    if (row >= BC) return;
    const size_t S = (size_t)BC * Rn;
    int lane = threadIdx.x & 31;
    float v[8];
    #pragma unroll
    for (int j = 0; j < 8; j++) {
        int c = lane + 32 * j;
        size_t o = (size_t)row * Rn + c;
        float x = a[o];
        if (NPA == 4) x += a[S + o] + a[2 * S + o] + a[3 * S + o] + ab[c];
        x += p2[o] + p2[S + o] + pb[c];
        v[j] = x;
    }
    float sum = 0.f;
    #pragma unroll
    for (int j = 0; j < 8; j++) sum += v[j];
    #pragma unroll
    for (int off = 16; off > 0; off >>= 1) sum += __shfl_xor_sync(0xffffffffu, sum, off);
    float mean = sum * (1.f / Rn);
    float q = 0.f;
    #pragma unroll
    for (int j = 0; j < 8; j++) { float d = v[j] - mean; q = fmaf(d, d, q); }
    #pragma unroll
    for (int off = 16; off > 0; off >>= 1) q += __shfl_xor_sync(0xffffffffu, q, off);
    float rstd = rsqrtf(q * (1.f / Rn) + 1e-5f);
    #pragma unroll
    for (int j = 0; j < 8; j++) {
        int c = lane + 32 * j;
        out[(size_t)row * Rn + c] = (v[j] - mean) * rstd * g[c] + be[c];
    }
}

// ---------------- megakernel ----------------
__global__ __launch_bounds__(NTHR)
void mega_kernel(const float* __restrict__ embs, const int* __restrict__ indices,
                 const int* __restrict__ mask, const float* __restrict__ host_cat,
                 const float* __restrict__ virus_cat, const float* __restrict__ extra_meta,
                 const float* __restrict__ fw,
                 const float* __restrict__ Wr, const float* __restrict__ br,
                 const float* __restrict__ Wqkv, const float* __restrict__ bqkv,
                 const float* __restrict__ Wo, const float* __restrict__ bo,
                 const float* __restrict__ ln1_g, const float* __restrict__ ln1_b,
                 const float* __restrict__ W1, const float* __restrict__ b1,
                 const float* __restrict__ W2, const float* __restrict__ b2,
                 const float* __restrict__ ln2_g, const float* __restrict__ ln2_b,
                 const float* __restrict__ Wc1, const float* __restrict__ bc1,
                 const float* __restrict__ Wc2, const float* __restrict__ bc2,
                 float* __restrict__ out) {
    __shared__ SmemU sm;
    const int tid = threadIdx.x;
    const int sub = tid >> 7;            // group in block: 0/1
    const int ltid = tid & 127;
    const int grp = blockIdx.x * 2 + sub;
    const int barid = 1 + sub;
    const int gid = blockIdx.x * NTHR + tid;

    // ---- P0: softmax weights per (b,c) segment ----
    if (gid < BC) {
        int bc = gid;
        float w[Sn]; int any = 0;
        #pragma unroll
        for (int s = 0; s < Sn; s++) {
            int m = mask[bc * Sn + s];
            any |= m;
            w[s] = m ? fw[indices[bc * Sn + s]] : -1e30f;
        }
        float mx = -1e30f;
        #pragma unroll
        for (int s = 0; s < Sn; s++) mx = fmaxf(mx, w[s]);
        float e[Sn], sum = 0.f;
        #pragma unroll
        for (int s = 0; s < Sn; s++) { e[s] = expf(w[s] - mx); sum += e[s]; }
        float inv = any ? (1.f / sum) : 0.f;
        #pragma unroll
        for (int s = 0; s < Sn; s++) g_aw[bc * Sn + s] = e[s] * inv;
    }
    gsync(0);

    // ---- P1: aggregation (HBM-bound) ----
    for (int u = gid; u < BC * (En / 4); u += NBLK * NTHR) {
        int bc = u / (En / 4);
        int col = u - bc * (En / 4);
        float aw[Sn];
        #pragma unroll
        for (int s = 0; s < Sn; s++) aw[s] = g_aw[bc * Sn + s];
        const float4* eb = (const float4*)embs + (size_t)bc * Sn * (En / 4) + col;
        float4 acc = make_float4(0.f, 0.f, 0.f, 0.f);
        #pragma unroll
        for (int s = 0; s < Sn; s++) {
            float4 v = eb[s * (En / 4)];
            acc.x = fmaf(aw[s], v.x, acc.x);
            acc.y = fmaf(aw[s], v.y, acc.y);
            acc.z = fmaf(aw[s], v.z, acc.z);
            acc.w = fmaf(aw[s], v.w, acc.w);
        }
        ((float4*)g_agg)[(size_t)bc * (En / 4) + col] = acc;
    }
    gsync(1);

    // ---- P2: x0 partials = agg @ Wr^T (split 4, KS=320) ----
    gemm_phase<0, false>(g_agg, nullptr, Wr, g_x0p, Rn, En, 4, 4, 320, 0,
                         &sm.g[sub].As[0][0][0], &sm.g[sub].Bs[0][0][0], ltid, barid, grp);
    gsync(2);

    // ---- P3: qkv partials = (sum4 x0p + br) @ Wqkv^T (split 2, KS=128) ----
    gemm_phase<4, false>(g_x0p, br, Wqkv, g_qkvp, QKVn, Rn, 12, 2, 128, (size_t)BC * Rn,
                         &sm.g[sub].As[0][0][0], &sm.g[sub].Bs[0][0][0], ltid, barid, grp);
    gsync(3);

    // ---- P4: attention ----
    attn_phase(&sm.a[sub], bqkv, ltid, barid, grp);
    gsync(4);

    // ---- P5: oproj partials = att @ Wo^T (split 2, KS=128) ----
    gemm_phase<0, false>(g_att, nullptr, Wo, g_opp, Rn, Rn, 4, 2, 128, 0,
                         &sm.g[sub].As[0][0][0], &sm.g[sub].Bs[0][0][0], ltid, barid, grp);
    gsync(5);

    // ---- P6: x1 = LN(sum4 x0p + br + sum2 opp + bo) ----
    ln_phase<4>(g_x0p, br, g_opp, bo, ln1_g, ln1_b, g_x1);
    gsync(6);

    // ---- P7: ff1 partials = x1 @ W1^T (split 2, KS=128) ----
    gemm_phase<0, false>(g_x1, nullptr, W1, g_ff1p, FFn, Rn, 8, 2, 128, 0,
                         &sm.g[sub].As[0][0][0], &sm.g[sub].Bs[0][0][0], ltid, barid, grp);
    gsync(7);

    // ---- P8: ff2 partials = relu(sum2 ff1p + b1) @ W2^T (split 2, KS=256) ----
    gemm_phase<2, true>(g_ff1p, b1, W2, g_fpp, Rn, FFn, 4, 2, 256, (size_t)BC * FFn,
                        &sm.g[sub].As[0][0][0], &sm.g[sub].Bs[0][0][0], ltid, barid, grp);
    gsync(8);

    // ---- P9: x2 = LN(x1 + sum2 fpp + b2) ----
    ln_phase<1>(g_x1, nullptr, g_fpp, b2, ln2_g, ln2_b, g_x2);
    gsync(9);

    // ---- P10: head layer 1: h[b][j] = relu(feat . Wc1[j] + bc1[j]) ----
    {
        int lane = ltid & 31, w = ltid >> 5;
        for (int u = grp; u < Bn * 4; u += NGRP) {
            int b = u >> 2, j0 = (u & 3) * 32;
            const float* xb = g_x2 + (size_t)b * Cn * Rn;
            const float* hc = host_cat + b * 64;
            const float* vc = virus_cat + b * 32;
            const float* mt = extra_meta + b * 3;
            for (int jj = w; jj < 32; jj += 4) {
                int j = j0 + jj;
                const float* wr = Wc1 + (size_t)j * HEAD_IN;
                float s = 0.f;
                for (int i = lane; i < Cn * Rn; i += 32) s = fmaf(wr[i], xb[i], s);
                for (int i = lane; i < 64; i += 32) s = fmaf(wr[Cn * Rn + i], hc[i], s);
                s = fmaf(wr[Cn * Rn + 64 + lane], vc[lane], s);
                if (lane < 3) s = fmaf(wr[Cn * Rn + 96 + lane], mt[lane], s);
                #pragma unroll
                for (int off = 16; off > 0; off >>= 1) s += __shfl_down_sync(0xffffffffu, s, off);
                if (lane == 0) g_h[b * 128 + j] = fmaxf(s + bc1[j], 0.f);
            }
        }
    }
    gsync(10);

    // ---- P11: logits ----
    {
        int gwarp = blockIdx.x * 8 + (tid >> 5);
        int lane = tid & 31;
        if (gwarp < Bn) {
            float v = 0.f;
            #pragma unroll
            for (int r = 0; r < 4; r++) {
                int i = lane + 32 * r;
                v = fmaf(g_h[gwarp * 128 + i], Wc2[i], v);
            }
            #pragma unroll
            for (int off = 16; off > 0; off >>= 1) v += __shfl_xor_sync(0xffffffffu, v, off);
            if (lane == 0) out[gwarp] = v + bc2[0];
        }
    }
}

// ---------------- launch ----------------
extern "C" void kernel_launch(void* const* d_in, const int* in_sizes, int n_in,
                              void* d_out, int out_size) {
    const float* embs        = (const float*)d_in[0];
    const int*   indices     = (const int*)d_in[1];
    const int*   mask        = (const int*)d_in[2];     // bool -> int32
    const float* host_cat    = (const float*)d_in[3];
    const float* virus_cat   = (const float*)d_in[4];
    const float* extra_meta  = (const float*)d_in[5];
    const float* func_weights= (const float*)d_in[6];
    const float* Wr          = (const float*)d_in[7];
    const float* br          = (const float*)d_in[8];
    const float* Wqkv        = (const float*)d_in[9];
    const float* bqkv        = (const float*)d_in[10];
    const float* Wo          = (const float*)d_in[11];
    const float* bo          = (const float*)d_in[12];
    const float* ln1_g       = (const float*)d_in[13];
    const float* ln1_b       = (const float*)d_in[14];
    const float* W1          = (const float*)d_in[15];
    const float* b1          = (const float*)d_in[16];
    const float* W2          = (const float*)d_in[17];
    const float* b2          = (const float*)d_in[18];
    const float* ln2_g       = (const float*)d_in[19];
    const float* ln2_b       = (const float*)d_in[20];
    const float* Wc1         = (const float*)d_in[21];
    const float* bc1         = (const float*)d_in[22];
    const float* Wc2         = (const float*)d_in[23];
    const float* bc2         = (const float*)d_in[24];
    float* out = (float*)d_out;

    mega_kernel<<<NBLK, NTHR>>>(embs, indices, mask, host_cat, virus_cat, extra_meta,
                                func_weights, Wr, br, Wqkv, bqkv, Wo, bo,
                                ln1_g, ln1_b, W1, b1, W2, b2, ln2_g, ln2_b,
                                Wc1, bc1, Wc2, bc2, out);
}